// round 2
// baseline (speedup 1.0000x reference)
#include <cuda_runtime.h>
#include <cstdint>
#include <cstddef>

// Problem constants
#define Bb 512
#define Tt 512
#define Ff 32
#define Hh 128
#define Ll 5
#define GH 256          // gate rows per CTA (half of 4H=512)
#define K2 80           // (H + F)/2 = 160/2 packed-k pairs
#define NTHREADS 256

// ---------------- smem layout ----------------
struct __align__(16) Smem {
    float2 wp[K2][GH];              // 163840 B: wp[k2][j] = (W[g][2k2], W[g][2k2+1]) transposed, k in [0,128)=W_hh, [128,160)=W_ih
    float  gh[2][8][GH];            // 16384 B: produced half-gates, double buffered
    float2 hx[K2][8];               // 5120 B:  hx[k2][r] = (state[r][2k2], state[r][2k2+1]); k<128 -> h, k>=128 -> x_t
    float  bias[GH];                // 1024 B
    unsigned long long mb_full[2];
    unsigned long long mb_free[2];
};

// ---------------- PTX helpers ----------------
__device__ __forceinline__ uint32_t smem_u32(const void* p) {
    return (uint32_t)__cvta_generic_to_shared(p);
}
__device__ __forceinline__ void mbar_init(uint32_t a, uint32_t cnt) {
    asm volatile("mbarrier.init.shared.b64 [%0], %1;" :: "r"(a), "r"(cnt) : "memory");
}
__device__ __forceinline__ void mbar_arrive_local(uint32_t a) {
    asm volatile("mbarrier.arrive.shared.b64 _, [%0];" :: "r"(a) : "memory");
}
// remote arrive on peer CTA's mbarrier at the same smem offset, release at cluster scope
__device__ __forceinline__ void mbar_arrive_remote(uint32_t a_local, uint32_t peer) {
    asm volatile(
        "{\n\t.reg .b32 ra;\n\t"
        "mapa.shared::cluster.u32 ra, %0, %1;\n\t"
        "mbarrier.arrive.release.cluster.shared::cluster.b64 _, [ra];\n\t}"
        :: "r"(a_local), "r"(peer) : "memory");
}
__device__ __forceinline__ void mbar_wait(uint32_t a, uint32_t parity) {
    asm volatile(
        "{\n\t.reg .pred P;\n"
        "W%=:\n\t"
        "mbarrier.try_wait.parity.acquire.cluster.shared::cta.b64 P, [%0], %1, 0x989680;\n\t"
        "@P bra D%=;\n\t"
        "bra W%=;\n"
        "D%=:\n\t}"
        :: "r"(a), "r"(parity) : "memory");
}
__device__ __forceinline__ uint32_t mapa_u32(uint32_t a, uint32_t rank) {
    uint32_t d;
    asm("mapa.shared::cluster.u32 %0, %1, %2;" : "=r"(d) : "r"(a), "r"(rank));
    return d;
}
__device__ __forceinline__ float ld_dsmem(uint32_t a) {
    float v;
    asm volatile("ld.shared::cluster.f32 %0, [%1];" : "=f"(v) : "r"(a));
    return v;
}
__device__ __forceinline__ void cluster_sync_() {
    asm volatile("barrier.cluster.arrive.aligned;" ::: "memory");
    asm volatile("barrier.cluster.wait.aligned;" ::: "memory");
}
// packed f32x2 FMA (Blackwell): d = a*b + c elementwise on float2 packed in b64
__device__ __forceinline__ unsigned long long ffma2(unsigned long long a,
                                                    unsigned long long b,
                                                    unsigned long long c) {
    unsigned long long d;
    asm("fma.rn.f32x2 %0, %1, %2, %3;" : "=l"(d) : "l"(a), "l"(b), "l"(c));
    return d;
}

__device__ __forceinline__ float sigf(float v) {
    return __fdividef(1.f, 1.f + __expf(-v));
}
__device__ __forceinline__ float tanh_fast(float v) {
    float a = fabsf(v);
    float e = __expf(-2.f * a);
    float r = __fdividef(1.f - e, 1.f + e);
    return copysignf(r, v);
}

// ---------------- kernel ----------------
// Grid: 128 CTAs, clusters of 2. Cluster c handles batch rows [8c, 8c+8).
// CTA rank r holds gate rows [256r, 256r+256) of {W_hh|W_ih} in smem (transposed,
// float2-packed over k). Per step: each CTA computes its 8x256 half-gate
// pre-activations, exchanges with peer (mbarrier full/free ring, double buffer),
// then both CTAs redundantly compute c/h for all 8 rows. c lives in registers.
__global__ void __launch_bounds__(NTHREADS, 1) __cluster_dims__(2, 1, 1)
lstm_kernel(const float* __restrict__ x,
            const float* __restrict__ W_ih,
            const float* __restrict__ W_hh,
            const float* __restrict__ b_ih,
            const float* __restrict__ b_hh,
            const float* __restrict__ W_fc,
            const float* __restrict__ b_fc,
            float* __restrict__ out)
{
    extern __shared__ unsigned char smem_raw[];
    Smem* s = reinterpret_cast<Smem*>(smem_raw);
    const int tid = threadIdx.x;
    uint32_t rank;
    asm("mov.u32 %0, %%cluster_ctarank;" : "=r"(rank));
    const uint32_t peer = rank ^ 1u;
    const int cid   = blockIdx.x >> 1;
    const int row0  = cid * 8;
    const int gbase = (int)rank * GH;   // my global gate-row offset

    // ---- prologue: load transposed/packed weights + bias, zero state ----
    for (int n = tid; n < K2 * GH; n += NTHREADS) {
        int k2 = n >> 8;
        int j  = n & (GH - 1);
        int g  = gbase + j;
        float2 v;
        if (k2 < Hh / 2) v = *reinterpret_cast<const float2*>(W_hh + g * Hh + 2 * k2);
        else             v = *reinterpret_cast<const float2*>(W_ih + g * Ff + 2 * (k2 - Hh / 2));
        s->wp[k2][j] = v;
    }
    if (tid < GH) s->bias[tid] = b_ih[gbase + tid] + b_hh[gbase + tid];
    for (int n = tid; n < K2 * 8; n += NTHREADS) s->hx[n >> 3][n & 7] = make_float2(0.f, 0.f);

    const uint32_t sb      = smem_u32(s);
    const uint32_t a_full0 = sb + (uint32_t)offsetof(Smem, mb_full);
    const uint32_t a_full1 = a_full0 + 8;
    const uint32_t a_free0 = sb + (uint32_t)offsetof(Smem, mb_free);
    const uint32_t a_free1 = a_free0 + 8;
    if (tid == 0) {
        mbar_init(a_full0, 1); mbar_init(a_full1, 1);
        mbar_init(a_free0, 1); mbar_init(a_free1, 1);
    }
    __syncthreads();
    cluster_sync_();                       // peers' mbarriers live before any remote arrive
    if (tid == 0) { mbar_arrive_local(a_free0); mbar_arrive_local(a_free1); }  // pre-arm "free"

    // x(t=0) into hx (k region [128,160))
    const int xr = tid >> 5, xf = tid & 31;
    const float* xptr = x + (size_t)(row0 + xr) * Tt * Ff + xf;
    {
        float v = xptr[0];
        __syncthreads();   // zero-fill complete before x overwrite
        reinterpret_cast<float*>(&s->hx[(Hh + xf) >> 1][xr])[xf & 1] = v;
    }
    __syncthreads();

    // ---- thread roles ----
    const int tx    = tid & 127;           // j-column (j = tx and tx+128)
    const int ty    = tid >> 7;            // row half: rows [4ty, 4ty+4)
    const int rbase = ty << 2;
    const unsigned long long* wq = reinterpret_cast<const unsigned long long*>(&s->wp[0][tx]);
    const unsigned long long* hq = reinterpret_cast<const unsigned long long*>(&s->hx[0][rbase]);
    const int hidx = tx;                   // h-update column
    const uint32_t gh_l  = sb + (uint32_t)offsetof(Smem, gh);
    const uint32_t gh_r0 = mapa_u32(gh_l, peer);
    const uint32_t gh_r1 = gh_r0 + (uint32_t)(8 * GH * 4);
    float c_[4] = {0.f, 0.f, 0.f, 0.f};    // cell state: rows ty, ty+2, ty+4, ty+6

    for (int t = 0; t < Tt; ++t) {
        // prefetch next step's x slice
        float xnext = 0.f;
        if (t + 1 < Tt) xnext = __ldg(xptr + (size_t)(t + 1) * Ff);

        // ---- half-gate GEMM: 4 rows x 2 cols per thread, f32x2 over k-pairs ----
        unsigned long long acc[4][2];
        #pragma unroll
        for (int q = 0; q < 4; ++q) { acc[q][0] = 0ull; acc[q][1] = 0ull; }
        #pragma unroll 20
        for (int k2 = 0; k2 < K2; ++k2) {
            unsigned long long w0 = wq[k2 * GH];          // j = tx      (conflict-free)
            unsigned long long w1 = wq[k2 * GH + 128];    // j = tx+128
            unsigned long long h0 = hq[k2 * 8 + 0];       // broadcast
            unsigned long long h1 = hq[k2 * 8 + 1];
            unsigned long long h2 = hq[k2 * 8 + 2];
            unsigned long long h3 = hq[k2 * 8 + 3];
            acc[0][0] = ffma2(h0, w0, acc[0][0]); acc[0][1] = ffma2(h0, w1, acc[0][1]);
            acc[1][0] = ffma2(h1, w0, acc[1][0]); acc[1][1] = ffma2(h1, w1, acc[1][1]);
            acc[2][0] = ffma2(h2, w0, acc[2][0]); acc[2][1] = ffma2(h2, w1, acc[2][1]);
            acc[3][0] = ffma2(h3, w0, acc[3][0]); acc[3][1] = ffma2(h3, w1, acc[3][1]);
        }

        const int p = t & 1;
        const uint32_t ph = (uint32_t)((t >> 1) & 1);
        const uint32_t a_free = p ? a_free1 : a_free0;
        const uint32_t a_full = p ? a_full1 : a_full0;

        // peer must have finished reading gh[p] from step t-2
        mbar_wait(a_free, ph);
        {
            float b0 = s->bias[tx], b1 = s->bias[tx + 128];
            #pragma unroll
            for (int q = 0; q < 4; ++q) {
                float2 v0 = *reinterpret_cast<float2*>(&acc[q][0]);
                float2 v1 = *reinterpret_cast<float2*>(&acc[q][1]);
                s->gh[p][rbase + q][tx]       = v0.x + v0.y + b0;
                s->gh[p][rbase + q][tx + 128] = v1.x + v1.y + b1;
            }
        }
        __syncthreads();
        if (tid == 0) mbar_arrive_remote(a_full, peer);   // my half is ready for peer
        mbar_wait(a_full, ph);                            // peer's half ready for me

        // ---- h/c update (redundant on both CTAs), peer half via DSMEM ----
        const float* lgh = &s->gh[p][0][0];
        const uint32_t rgh = p ? gh_r1 : gh_r0;
        float aL0[4], aL1[4], aR0[4], aR1[4];
        #pragma unroll
        for (int q = 0; q < 4; ++q) {
            int r = ty + 2 * q;
            aR0[q] = ld_dsmem(rgh + (uint32_t)((r * GH + hidx) * 4));
            aR1[q] = ld_dsmem(rgh + (uint32_t)((r * GH + 128 + hidx) * 4));
            aL0[q] = lgh[r * GH + hidx];
            aL1[q] = lgh[r * GH + 128 + hidx];
        }
        #pragma unroll
        for (int q = 0; q < 4; ++q) {
            int r = ty + 2 * q;
            // rank0 holds (i,f); rank1 holds (g,o)
            float iv = rank ? aR0[q] : aL0[q];
            float fv = rank ? aR1[q] : aL1[q];
            float gv = rank ? aL0[q] : aR0[q];
            float ov = rank ? aL1[q] : aR1[q];
            float c = sigf(fv) * c_[q] + sigf(iv) * tanh_fast(gv);
            c_[q] = c;
            float h = sigf(ov) * tanh_fast(c);
            reinterpret_cast<float*>(&s->hx[hidx >> 1][r])[hidx & 1] = h;
        }
        if (t + 1 < Tt)
            reinterpret_cast<float*>(&s->hx[(Hh + xf) >> 1][xr])[xf & 1] = xnext;
        __syncthreads();
        if (tid == 0) mbar_arrive_remote(a_free, peer);   // done reading peer's gh[p]
    }

    // ---- FC head on final h (rank 0 only) ----
    if (rank == 0 && tid < 8 * Ll) {
        int r = tid / Ll, l = tid - r * Ll;
        float acc = b_fc[l];
        const float* wl = W_fc + l * Hh;
        #pragma unroll 16
        for (int k = 0; k < Hh; ++k)
            acc += reinterpret_cast<const float*>(&s->hx[k >> 1][r])[k & 1] * wl[k];
        out[(row0 + r) * Ll + l] = acc;
    }
    cluster_sync_();   // keep peer smem alive until all remote ops drained
}

// ---------------- host launch ----------------
extern "C" void kernel_launch(void* const* d_in, const int* in_sizes, int n_in,
                              void* d_out, int out_size) {
    const float* x    = (const float*)d_in[0];
    const float* W_ih = (const float*)d_in[1];
    const float* W_hh = (const float*)d_in[2];
    const float* b_ih = (const float*)d_in[3];
    const float* b_hh = (const float*)d_in[4];
    const float* W_fc = (const float*)d_in[5];
    const float* b_fc = (const float*)d_in[6];
    float* out = (float*)d_out;

    const size_t smem = sizeof(Smem);
    cudaFuncSetAttribute(lstm_kernel, cudaFuncAttributeMaxDynamicSharedMemorySize, (int)smem);
    lstm_kernel<<<128, NTHREADS, smem>>>(x, W_ih, W_hh, b_ih, b_hh, W_fc, b_fc, out);
}

// round 4
// speedup vs baseline: 1.0234x; 1.0234x over previous
#include <cuda_runtime.h>
#include <cstdint>
#include <cstddef>

// Problem constants
#define Bb 512
#define Tt 512
#define Ff 32
#define Hh 128
#define Ll 5
#define GH 256          // gate rows per CTA (half of 4H=512)
#define K2 80           // (H + F)/2 = 160/2 packed-k pairs
#define NTHREADS 256

// ---------------- smem layout ----------------
// Weights now live in registers; smem holds only the exchange buffers + state.
struct __align__(16) Smem {
    float  gh[2][8][GH];            // 16384 B: produced half-gates, double buffered
    float2 hx[K2][8];               // 5120 B:  hx[k2][r] = (state[r][2k2], state[r][2k2+1]); k<128 -> h, k>=128 -> x_t
    unsigned long long mb_full[2];
    unsigned long long mb_free[2];
};

// ---------------- PTX helpers ----------------
__device__ __forceinline__ uint32_t smem_u32(const void* p) {
    return (uint32_t)__cvta_generic_to_shared(p);
}
__device__ __forceinline__ void mbar_init(uint32_t a, uint32_t cnt) {
    asm volatile("mbarrier.init.shared.b64 [%0], %1;" :: "r"(a), "r"(cnt) : "memory");
}
__device__ __forceinline__ void mbar_arrive_local(uint32_t a) {
    asm volatile("mbarrier.arrive.shared.b64 _, [%0];" :: "r"(a) : "memory");
}
// remote arrive on peer CTA's mbarrier at the same smem offset, release at cluster scope
__device__ __forceinline__ void mbar_arrive_remote(uint32_t a_local, uint32_t peer) {
    asm volatile(
        "{\n\t.reg .b32 ra;\n\t"
        "mapa.shared::cluster.u32 ra, %0, %1;\n\t"
        "mbarrier.arrive.release.cluster.shared::cluster.b64 _, [ra];\n\t}"
        :: "r"(a_local), "r"(peer) : "memory");
}
__device__ __forceinline__ void mbar_wait(uint32_t a, uint32_t parity) {
    asm volatile(
        "{\n\t.reg .pred P;\n"
        "W%=:\n\t"
        "mbarrier.try_wait.parity.acquire.cluster.shared::cta.b64 P, [%0], %1, 0x989680;\n\t"
        "@P bra D%=;\n\t"
        "bra W%=;\n"
        "D%=:\n\t}"
        :: "r"(a), "r"(parity) : "memory");
}
__device__ __forceinline__ uint32_t mapa_u32(uint32_t a, uint32_t rank) {
    uint32_t d;
    asm("mapa.shared::cluster.u32 %0, %1, %2;" : "=r"(d) : "r"(a), "r"(rank));
    return d;
}
__device__ __forceinline__ float ld_dsmem(uint32_t a) {
    float v;
    asm volatile("ld.shared::cluster.f32 %0, [%1];" : "=f"(v) : "r"(a));
    return v;
}
__device__ __forceinline__ void cluster_sync_() {
    asm volatile("barrier.cluster.arrive.aligned;" ::: "memory");
    asm volatile("barrier.cluster.wait.aligned;" ::: "memory");
}
// packed f32x2 FMA (Blackwell): d = a*b + c elementwise on float2 packed in b64
__device__ __forceinline__ unsigned long long ffma2(unsigned long long a,
                                                    unsigned long long b,
                                                    unsigned long long c) {
    unsigned long long d;
    asm("fma.rn.f32x2 %0, %1, %2, %3;" : "=l"(d) : "l"(a), "l"(b), "l"(c));
    return d;
}

__device__ __forceinline__ float sigf(float v) {
    return __fdividef(1.f, 1.f + __expf(-v));
}
__device__ __forceinline__ float tanh_fast(float v) {
    float a = fabsf(v);
    float e = __expf(-2.f * a);
    float r = __fdividef(1.f - e, 1.f + e);
    return copysignf(r, v);
}

// ---------------- kernel ----------------
// Grid: 128 CTAs, clusters of 2. Cluster c handles batch rows [8c, 8c+8).
// CTA rank r holds gate rows [256r, 256r+256). Each thread owns ONE gate row
// (j = tid): its 160 weights live in 80 f32x2 REGISTERS for the entire kernel.
// Per step: thread computes its 8 gate pre-activations (8 rows x 1 gate) from
// register weights + broadcast LDS.128 of h-state, writes them to gh, exchanges
// with the peer CTA (mbarrier full/free ring, double buffer), then both CTAs
// redundantly compute the c/h update. c lives in registers.
__global__ void __launch_bounds__(NTHREADS, 1) __cluster_dims__(2, 1, 1)
lstm_kernel(const float* __restrict__ x,
            const float* __restrict__ W_ih,
            const float* __restrict__ W_hh,
            const float* __restrict__ b_ih,
            const float* __restrict__ b_hh,
            const float* __restrict__ W_fc,
            const float* __restrict__ b_fc,
            float* __restrict__ out)
{
    __shared__ Smem smem_s;
    Smem* s = &smem_s;
    const int tid = threadIdx.x;
    uint32_t rank;
    asm("mov.u32 %0, %%cluster_ctarank;" : "=r"(rank));
    const uint32_t peer = rank ^ 1u;
    const int cid   = blockIdx.x >> 1;
    const int row0  = cid * 8;
    const int gbase = (int)rank * GH;   // my global gate-row offset
    const int g     = gbase + tid;      // my gate row

    // ---- prologue: my 160 weights -> 80 packed f32x2 registers ----
    unsigned long long Wr[K2];
    {
        const unsigned long long* whh =
            reinterpret_cast<const unsigned long long*>(W_hh + (size_t)g * Hh);
        #pragma unroll
        for (int k = 0; k < Hh / 2; ++k) Wr[k] = __ldg(whh + k);
        const unsigned long long* wih =
            reinterpret_cast<const unsigned long long*>(W_ih + (size_t)g * Ff);
        #pragma unroll
        for (int k = 0; k < Ff / 2; ++k) Wr[Hh / 2 + k] = __ldg(wih + k);
    }
    const float bj = b_ih[g] + b_hh[g];

    // zero state
    for (int n = tid; n < K2 * 8; n += NTHREADS) s->hx[n >> 3][n & 7] = make_float2(0.f, 0.f);

    const uint32_t sb      = smem_u32(s);
    const uint32_t a_full0 = sb + (uint32_t)offsetof(Smem, mb_full);
    const uint32_t a_full1 = a_full0 + 8;
    const uint32_t a_free0 = sb + (uint32_t)offsetof(Smem, mb_free);
    const uint32_t a_free1 = a_free0 + 8;
    if (tid == 0) {
        mbar_init(a_full0, 1); mbar_init(a_full1, 1);
        mbar_init(a_free0, 1); mbar_init(a_free1, 1);
    }
    __syncthreads();
    cluster_sync_();                       // peers' mbarriers live before any remote arrive
    if (tid == 0) { mbar_arrive_local(a_free0); mbar_arrive_local(a_free1); }  // pre-arm "free"

    // x(t=0) into hx (k region [128,160))
    const int xr = tid >> 5, xf = tid & 31;
    const float* xptr = x + (size_t)(row0 + xr) * Tt * Ff + xf;
    {
        float v = xptr[0];
        __syncthreads();   // zero-fill complete before x overwrite
        reinterpret_cast<float*>(&s->hx[(Hh + xf) >> 1][xr])[xf & 1] = v;
    }
    __syncthreads();

    // ---- thread roles for the update phase ----
    const int tx    = tid & 127;           // h column
    const int ty    = tid >> 7;            // row parity: rows ty, ty+2, ty+4, ty+6
    const int hidx  = tx;
    const uint32_t gh_l  = sb + (uint32_t)offsetof(Smem, gh);
    const uint32_t gh_r0 = mapa_u32(gh_l, peer);
    const uint32_t gh_r1 = gh_r0 + (uint32_t)(8 * GH * 4);
    const ulonglong2* hq = reinterpret_cast<const ulonglong2*>(&s->hx[0][0]);
    float c_[4] = {0.f, 0.f, 0.f, 0.f};    // cell state: rows ty, ty+2, ty+4, ty+6

    for (int t = 0; t < Tt; ++t) {
        // prefetch next step's x slice
        float xnext = 0.f;
        if (t + 1 < Tt) xnext = __ldg(xptr + (size_t)(t + 1) * Ff);

        // ---- gate GEMM: 8 rows x 1 gate per thread, weights in registers ----
        unsigned long long acc[8];
        #pragma unroll
        for (int r = 0; r < 8; ++r) acc[r] = 0ull;
        #pragma unroll
        for (int k2 = 0; k2 < K2; ++k2) {
            ulonglong2 hA = hq[k2 * 4 + 0];   // rows 0,1  (broadcast LDS.128)
            ulonglong2 hB = hq[k2 * 4 + 1];   // rows 2,3
            ulonglong2 hC = hq[k2 * 4 + 2];   // rows 4,5
            ulonglong2 hD = hq[k2 * 4 + 3];   // rows 6,7
            unsigned long long w = Wr[k2];
            acc[0] = ffma2(hA.x, w, acc[0]); acc[1] = ffma2(hA.y, w, acc[1]);
            acc[2] = ffma2(hB.x, w, acc[2]); acc[3] = ffma2(hB.y, w, acc[3]);
            acc[4] = ffma2(hC.x, w, acc[4]); acc[5] = ffma2(hC.y, w, acc[5]);
            acc[6] = ffma2(hD.x, w, acc[6]); acc[7] = ffma2(hD.y, w, acc[7]);
        }

        const int p = t & 1;
        const uint32_t ph = (uint32_t)((t >> 1) & 1);
        const uint32_t a_free = p ? a_free1 : a_free0;
        const uint32_t a_full = p ? a_full1 : a_full0;

        // peer must have finished reading gh[p] from step t-2
        mbar_wait(a_free, ph);
        #pragma unroll
        for (int r = 0; r < 8; ++r) {
            float2 v = *reinterpret_cast<float2*>(&acc[r]);
            s->gh[p][r][tid] = v.x + v.y + bj;
        }
        __syncthreads();
        if (tid == 0) mbar_arrive_remote(a_full, peer);   // my half is ready for peer
        mbar_wait(a_full, ph);                            // peer's half ready for me

        // ---- h/c update (redundant on both CTAs), peer half via DSMEM ----
        const float* lgh = &s->gh[p][0][0];
        const uint32_t rgh = p ? gh_r1 : gh_r0;
        float aL0[4], aL1[4], aR0[4], aR1[4];
        #pragma unroll
        for (int q = 0; q < 4; ++q) {
            int r = ty + 2 * q;
            aR0[q] = ld_dsmem(rgh + (uint32_t)((r * GH + hidx) * 4));
            aR1[q] = ld_dsmem(rgh + (uint32_t)((r * GH + 128 + hidx) * 4));
            aL0[q] = lgh[r * GH + hidx];
            aL1[q] = lgh[r * GH + 128 + hidx];
        }
        #pragma unroll
        for (int q = 0; q < 4; ++q) {
            int r = ty + 2 * q;
            // rank0 holds (i,f); rank1 holds (g,o)
            float iv = rank ? aR0[q] : aL0[q];
            float fv = rank ? aR1[q] : aL1[q];
            float gv = rank ? aL0[q] : aR0[q];
            float ov = rank ? aL1[q] : aR1[q];
            float c = sigf(fv) * c_[q] + sigf(iv) * tanh_fast(gv);
            c_[q] = c;
            float h = sigf(ov) * tanh_fast(c);
            reinterpret_cast<float*>(&s->hx[hidx >> 1][r])[hidx & 1] = h;
        }
        if (t + 1 < Tt)
            reinterpret_cast<float*>(&s->hx[(Hh + xf) >> 1][xr])[xf & 1] = xnext;
        __syncthreads();
        if (tid == 0) mbar_arrive_remote(a_free, peer);   // done reading peer's gh[p]
    }

    // ---- FC head on final h (rank 0 only) ----
    if (rank == 0 && tid < 8 * Ll) {
        int r = tid / Ll, l = tid - r * Ll;
        float acc = b_fc[l];
        const float* wl = W_fc + l * Hh;
        #pragma unroll 16
        for (int k = 0; k < Hh; ++k)
            acc += reinterpret_cast<const float*>(&s->hx[k >> 1][r])[k & 1] * wl[k];
        out[(row0 + r) * Ll + l] = acc;
    }
    cluster_sync_();   // keep peer smem alive until all remote ops drained
}

// ---------------- host launch ----------------
extern "C" void kernel_launch(void* const* d_in, const int* in_sizes, int n_in,
                              void* d_out, int out_size) {
    const float* x    = (const float*)d_in[0];
    const float* W_ih = (const float*)d_in[1];
    const float* W_hh = (const float*)d_in[2];
    const float* b_ih = (const float*)d_in[3];
    const float* b_hh = (const float*)d_in[4];
    const float* W_fc = (const float*)d_in[5];
    const float* b_fc = (const float*)d_in[6];
    float* out = (float*)d_out;

    lstm_kernel<<<128, NTHREADS>>>(x, W_ih, W_hh, b_ih, b_hh, W_fc, b_fc, out);
}

// round 6
// speedup vs baseline: 1.7408x; 1.7009x over previous
#include <cuda_runtime.h>
#include <cstdint>

// Problem constants
#define Bb 512
#define Tt 512
#define Ff 32
#define Hh 128
#define Ll 5
#define G4 512          // total gate rows (4H)
#define ROWS 4          // batch rows per CTA
#define K2T 80          // (H+F)/2 total packed k-pairs (k2 0..63 = W_hh, 64..79 = W_ih)
#define K2H 40          // k-pairs per k-half
#define NTHREADS 512

// ---------------- smem layout ----------------
struct __align__(16) Smem {
    float2 wsm[2][K2H][256];   // 163840 B: weights of gates [256,512), wsm[kh][kk][g-256]
    float2 hx[K2T][ROWS];      // 2560 B: hx[k2][r]; k<128 -> h, k>=128 -> x_t
    float  red[ROWS][G4];      // 8192 B: k-half-1 partial sums
    float  gh[ROWS][G4];       // 8192 B: gate pre-activations, i|f|g|o blocks of 128
};
// total 182,784 B (dynamic smem)

// packed f32x2 FMA (Blackwell)
__device__ __forceinline__ unsigned long long ffma2(unsigned long long a,
                                                    unsigned long long b,
                                                    unsigned long long c) {
    unsigned long long d;
    asm("fma.rn.f32x2 %0, %1, %2, %3;" : "=l"(d) : "l"(a), "l"(b), "l"(c));
    return d;
}
__device__ __forceinline__ float hsum2(unsigned long long a) {
    float2 v = *reinterpret_cast<float2*>(&a);
    return v.x + v.y;
}
__device__ __forceinline__ float sigf(float v) {
    return __fdividef(1.f, 1.f + __expf(-v));
}
__device__ __forceinline__ float tanh_fast(float v) {
    float a = fabsf(v);
    float e = __expf(-2.f * a);
    float r = __fdividef(1.f - e, 1.f + e);
    return copysignf(r, v);
}

// ---------------- kernel ----------------
// 128 CTAs x 512 threads, NO clusters. CTA b owns batch rows [4b, 4b+4) and all
// 512 gate rows. Thread t: k-half kh = t>>8, gate rows g0 = t&255 and g0+256.
// Gate g0's k-half weights live in 40 f32x2 REGISTERS; gate (g0+256)'s k-half
// weights are read from smem (conflict-free). Per step:
//   GEMM: 40 iters x (2 broadcast LDS.128 h + 1 LDS.64 w + 8 FFMA2)
//   kh=1 writes partials to red; sync; kh=0 adds + bias -> gh; sync;
//   update: 1 (row,col) item per thread, c in a register, h -> hx; sync.
__global__ void __launch_bounds__(NTHREADS, 1)
lstm_kernel(const float* __restrict__ x,
            const float* __restrict__ W_ih,
            const float* __restrict__ W_hh,
            const float* __restrict__ b_ih,
            const float* __restrict__ b_hh,
            const float* __restrict__ W_fc,
            const float* __restrict__ b_fc,
            float* __restrict__ out)
{
    extern __shared__ unsigned char smem_raw[];
    Smem* s = reinterpret_cast<Smem*>(smem_raw);
    const int tid  = threadIdx.x;
    const int kh   = tid >> 8;          // k-half: 0 -> k2 [0,40), 1 -> k2 [40,80)
    const int g0   = tid & 255;         // gate rows g0 (regs), g0+256 (smem)
    const int row0 = blockIdx.x * ROWS;

    // ---- prologue: gate g0's k-half -> registers; gate g0+256's k-half -> smem ----
    const float2* whh2 = reinterpret_cast<const float2*>(W_hh);   // row g: 64 float2
    const float2* wih2 = reinterpret_cast<const float2*>(W_ih);   // row g: 16 float2
    unsigned long long Wr0[K2H];
    {
        const int base = kh * K2H;
        #pragma unroll
        for (int kk = 0; kk < K2H; ++kk) {
            int k2 = base + kk;
            float2 v0 = (k2 < 64) ? __ldg(whh2 + (size_t)g0 * 64 + k2)
                                  : __ldg(wih2 + (size_t)g0 * 16 + (k2 - 64));
            Wr0[kk] = *reinterpret_cast<unsigned long long*>(&v0);
            int g1 = g0 + 256;
            float2 v1 = (k2 < 64) ? __ldg(whh2 + (size_t)g1 * 64 + k2)
                                  : __ldg(wih2 + (size_t)g1 * 16 + (k2 - 64));
            s->wsm[kh][kk][g0] = v1;
        }
    }
    const float bj0 = b_ih[g0] + b_hh[g0];
    const float bj1 = b_ih[g0 + 256] + b_hh[g0 + 256];

    // ---- init state: zero h region (k2 0..63), x(t=0) into k2 64..79 ----
    if (tid < 256) s->hx[tid >> 2][tid & 3] = make_float2(0.f, 0.f);
    const int xr = (tid >> 5) & 3, xf = tid & 31;          // loader role for tid<128
    const float* xptr = x + (size_t)(row0 + xr) * Tt * Ff + xf;
    if (tid < 128) {
        float v = __ldg(xptr);
        reinterpret_cast<float*>(&s->hx[64 + (xf >> 1)][xr])[xf & 1] = v;
    }
    __syncthreads();

    // ---- update-phase roles ----
    const int ur = tid >> 7;            // batch row of my update item
    const int uj = tid & 127;           // h column of my update item
    float c_ = 0.f;

    const unsigned long long* hq =
        reinterpret_cast<const unsigned long long*>(&s->hx[kh * K2H][0]);
    const unsigned long long* wp =
        reinterpret_cast<const unsigned long long*>(&s->wsm[kh][0][g0]);

    for (int st = 0; st < Tt; ++st) {
        // prefetch next x slice (tid<128)
        float xnext = 0.f;
        if (tid < 128 && st + 1 < Tt) xnext = __ldg(xptr + (size_t)(st + 1) * Ff);

        // ---- GEMM: 2 gate rows x 4 batch rows, my k-half ----
        unsigned long long a0[ROWS], a1[ROWS];
        #pragma unroll
        for (int r = 0; r < ROWS; ++r) { a0[r] = 0ull; a1[r] = 0ull; }
        #pragma unroll
        for (int kk = 0; kk < K2H; ++kk) {
            ulonglong2 hAB = *reinterpret_cast<const ulonglong2*>(hq + kk * 4);     // rows 0,1
            ulonglong2 hCD = *reinterpret_cast<const ulonglong2*>(hq + kk * 4 + 2); // rows 2,3
            unsigned long long w0 = Wr0[kk];
            unsigned long long w1 = wp[(size_t)kk * 256];
            a0[0] = ffma2(hAB.x, w0, a0[0]); a0[1] = ffma2(hAB.y, w0, a0[1]);
            a0[2] = ffma2(hCD.x, w0, a0[2]); a0[3] = ffma2(hCD.y, w0, a0[3]);
            a1[0] = ffma2(hAB.x, w1, a1[0]); a1[1] = ffma2(hAB.y, w1, a1[1]);
            a1[2] = ffma2(hCD.x, w1, a1[2]); a1[3] = ffma2(hCD.y, w1, a1[3]);
        }

        // ---- combine k-halves ----
        if (kh == 1) {
            #pragma unroll
            for (int r = 0; r < ROWS; ++r) {
                s->red[r][g0]       = hsum2(a0[r]);
                s->red[r][g0 + 256] = hsum2(a1[r]);
            }
        }
        __syncthreads();
        if (kh == 0) {
            #pragma unroll
            for (int r = 0; r < ROWS; ++r) {
                s->gh[r][g0]       = hsum2(a0[r]) + s->red[r][g0]       + bj0;
                s->gh[r][g0 + 256] = hsum2(a1[r]) + s->red[r][g0 + 256] + bj1;
            }
        }
        __syncthreads();

        // ---- h/c update: one (row, col) item per thread ----
        {
            float iv = s->gh[ur][uj];
            float fv = s->gh[ur][uj + 128];
            float gv = s->gh[ur][uj + 256];
            float ov = s->gh[ur][uj + 384];
            float c = sigf(fv) * c_ + sigf(iv) * tanh_fast(gv);
            c_ = c;
            float h = sigf(ov) * tanh_fast(c);
            reinterpret_cast<float*>(&s->hx[uj >> 1][ur])[uj & 1] = h;
        }
        if (tid < 128 && st + 1 < Tt)
            reinterpret_cast<float*>(&s->hx[64 + (xf >> 1)][xr])[xf & 1] = xnext;
        __syncthreads();
    }

    // ---- FC head on final h ----
    if (tid < ROWS * Ll) {
        int r = tid / Ll, l = tid - r * Ll;
        float acc = b_fc[l];
        const float* wl = W_fc + l * Hh;
        #pragma unroll 16
        for (int k = 0; k < Hh; ++k)
            acc += reinterpret_cast<const float*>(&s->hx[k >> 1][r])[k & 1] * wl[k];
        out[(row0 + r) * Ll + l] = acc;
    }
}

// ---------------- host launch ----------------
extern "C" void kernel_launch(void* const* d_in, const int* in_sizes, int n_in,
                              void* d_out, int out_size) {
    const float* x    = (const float*)d_in[0];
    const float* W_ih = (const float*)d_in[1];
    const float* W_hh = (const float*)d_in[2];
    const float* b_ih = (const float*)d_in[3];
    const float* b_hh = (const float*)d_in[4];
    const float* W_fc = (const float*)d_in[5];
    const float* b_fc = (const float*)d_in[6];
    float* out = (float*)d_out;

    const size_t smem = sizeof(Smem);
    cudaFuncSetAttribute(lstm_kernel, cudaFuncAttributeMaxDynamicSharedMemorySize, (int)smem);
    lstm_kernel<<<Bb / ROWS, NTHREADS, smem>>>(x, W_ih, W_hh, b_ih, b_hh, W_fc, b_fc, out);
}

// round 7
// speedup vs baseline: 1.7441x; 1.0019x over previous
#include <cuda_runtime.h>
#include <cstdint>

// Problem constants
#define Bb 512
#define Tt 512
#define Ff 32
#define Hh 128
#define Ll 5
#define G4 512          // total gate rows (4H)
#define ROWS 4          // batch rows per CTA
#define K2T 80          // (H+F)/2 total packed k-pairs (k2 0..63 = W_hh, 64..79 = W_ih)
#define K2H 40          // k-pairs per k-half
#define NTHREADS 512

// ---------------- smem layout ----------------
struct __align__(16) Smem {
    float2 wsm[2][K2H][256];   // 163840 B: weights of gates [256,512), wsm[kh][kk][g-256]
    float2 hx[K2T][ROWS];      // 2560 B: hx[k2][r]; k<128 -> h, k>=128 -> x_t
    float  red[2][ROWS][G4];   // 16384 B: per-k-half partial sums (kh=0 carries bias)
};
// total 182,784 B (dynamic smem)

// packed f32x2 FMA (Blackwell)
__device__ __forceinline__ unsigned long long ffma2(unsigned long long a,
                                                    unsigned long long b,
                                                    unsigned long long c) {
    unsigned long long d;
    asm("fma.rn.f32x2 %0, %1, %2, %3;" : "=l"(d) : "l"(a), "l"(b), "l"(c));
    return d;
}
__device__ __forceinline__ float hsum2(unsigned long long a) {
    float2 v = *reinterpret_cast<float2*>(&a);
    return v.x + v.y;
}
__device__ __forceinline__ float sigf(float v) {
    return __fdividef(1.f, 1.f + __expf(-v));
}
__device__ __forceinline__ float tanh_fast(float v) {
    float a = fabsf(v);
    float e = __expf(-2.f * a);
    float r = __fdividef(1.f - e, 1.f + e);
    return copysignf(r, v);
}

// ---------------- kernel ----------------
// 128 CTAs x 512 threads, NO clusters. CTA b owns batch rows [4b, 4b+4) and all
// 512 gate rows. Thread t: k-half kh = t>>8, gate rows g0 = t&255 and g0+256.
// Gate g0's k-half weights live in 40 f32x2 REGISTERS; gate (g0+256)'s k-half
// weights are read from smem (conflict-free). Per step (2 syncs only):
//   GEMM: 40 iters x (2 broadcast LDS.128 h + 1 LDS.64 w + 8 FFMA2)
//   both k-halves write bias-folded partials to red[kh]; sync;
//   update: 1 (row,col) item per thread reads red[0]+red[1] for its 4 gates,
//   c in a register, h -> hx; sync.
__global__ void __launch_bounds__(NTHREADS, 1)
lstm_kernel(const float* __restrict__ x,
            const float* __restrict__ W_ih,
            const float* __restrict__ W_hh,
            const float* __restrict__ b_ih,
            const float* __restrict__ b_hh,
            const float* __restrict__ W_fc,
            const float* __restrict__ b_fc,
            float* __restrict__ out)
{
    extern __shared__ unsigned char smem_raw[];
    Smem* s = reinterpret_cast<Smem*>(smem_raw);
    const int tid  = threadIdx.x;
    const int kh   = tid >> 8;          // k-half: 0 -> k2 [0,40), 1 -> k2 [40,80)
    const int g0   = tid & 255;         // gate rows g0 (regs), g0+256 (smem)
    const int row0 = blockIdx.x * ROWS;

    // ---- prologue: gate g0's k-half -> registers; gate g0+256's k-half -> smem ----
    const float2* whh2 = reinterpret_cast<const float2*>(W_hh);   // row g: 64 float2
    const float2* wih2 = reinterpret_cast<const float2*>(W_ih);   // row g: 16 float2
    unsigned long long Wr0[K2H];
    {
        const int base = kh * K2H;
        #pragma unroll
        for (int kk = 0; kk < K2H; ++kk) {
            int k2 = base + kk;
            float2 v0 = (k2 < 64) ? __ldg(whh2 + (size_t)g0 * 64 + k2)
                                  : __ldg(wih2 + (size_t)g0 * 16 + (k2 - 64));
            Wr0[kk] = *reinterpret_cast<unsigned long long*>(&v0);
            int g1 = g0 + 256;
            float2 v1 = (k2 < 64) ? __ldg(whh2 + (size_t)g1 * 64 + k2)
                                  : __ldg(wih2 + (size_t)g1 * 16 + (k2 - 64));
            s->wsm[kh][kk][g0] = v1;
        }
    }
    // bias folded into kh=0's partial only
    const float cb0 = (kh == 0) ? (b_ih[g0] + b_hh[g0]) : 0.f;
    const float cb1 = (kh == 0) ? (b_ih[g0 + 256] + b_hh[g0 + 256]) : 0.f;

    // ---- init state: zero h region (k2 0..63), x(t=0) into k2 64..79 ----
    if (tid < 256) s->hx[tid >> 2][tid & 3] = make_float2(0.f, 0.f);
    const int xr = (tid >> 5) & 3, xf = tid & 31;          // loader role for tid<128
    const float* xptr = x + (size_t)(row0 + xr) * Tt * Ff + xf;
    if (tid < 128) {
        float v = __ldg(xptr);
        reinterpret_cast<float*>(&s->hx[64 + (xf >> 1)][xr])[xf & 1] = v;
    }
    __syncthreads();

    // ---- update-phase roles ----
    const int ur = tid >> 7;            // batch row of my update item
    const int uj = tid & 127;           // h column of my update item
    float c_ = 0.f;

    const unsigned long long* hq =
        reinterpret_cast<const unsigned long long*>(&s->hx[kh * K2H][0]);
    const unsigned long long* wp =
        reinterpret_cast<const unsigned long long*>(&s->wsm[kh][0][g0]);

    for (int st = 0; st < Tt; ++st) {
        // prefetch next x slice (tid<128)
        float xnext = 0.f;
        if (tid < 128 && st + 1 < Tt) xnext = __ldg(xptr + (size_t)(st + 1) * Ff);

        // ---- GEMM: 2 gate rows x 4 batch rows, my k-half ----
        unsigned long long a0[ROWS], a1[ROWS];
        #pragma unroll
        for (int r = 0; r < ROWS; ++r) { a0[r] = 0ull; a1[r] = 0ull; }
        #pragma unroll
        for (int kk = 0; kk < K2H; ++kk) {
            ulonglong2 hAB = *reinterpret_cast<const ulonglong2*>(hq + kk * 4);     // rows 0,1
            ulonglong2 hCD = *reinterpret_cast<const ulonglong2*>(hq + kk * 4 + 2); // rows 2,3
            unsigned long long w0 = Wr0[kk];
            unsigned long long w1 = wp[(size_t)kk * 256];
            a0[0] = ffma2(hAB.x, w0, a0[0]); a0[1] = ffma2(hAB.y, w0, a0[1]);
            a0[2] = ffma2(hCD.x, w0, a0[2]); a0[3] = ffma2(hCD.y, w0, a0[3]);
            a1[0] = ffma2(hAB.x, w1, a1[0]); a1[1] = ffma2(hAB.y, w1, a1[1]);
            a1[2] = ffma2(hCD.x, w1, a1[2]); a1[3] = ffma2(hCD.y, w1, a1[3]);
        }

        // ---- single-pass partial write (bias folded into kh=0) ----
        #pragma unroll
        for (int r = 0; r < ROWS; ++r) {
            s->red[kh][r][g0]       = hsum2(a0[r]) + cb0;
            s->red[kh][r][g0 + 256] = hsum2(a1[r]) + cb1;
        }
        __syncthreads();

        // ---- h/c update: one (row, col) item per thread, sums both k-halves ----
        {
            const float* r0 = &s->red[0][ur][0];
            const float* r1 = &s->red[1][ur][0];
            float iv = r0[uj]       + r1[uj];
            float fv = r0[uj + 128] + r1[uj + 128];
            float gv = r0[uj + 256] + r1[uj + 256];
            float ov = r0[uj + 384] + r1[uj + 384];
            float c = sigf(fv) * c_ + sigf(iv) * tanh_fast(gv);
            c_ = c;
            float h = sigf(ov) * tanh_fast(c);
            reinterpret_cast<float*>(&s->hx[uj >> 1][ur])[uj & 1] = h;
        }
        if (tid < 128 && st + 1 < Tt)
            reinterpret_cast<float*>(&s->hx[64 + (xf >> 1)][xr])[xf & 1] = xnext;
        __syncthreads();
    }

    // ---- FC head on final h ----
    if (tid < ROWS * Ll) {
        int r = tid / Ll, l = tid - r * Ll;
        float acc = b_fc[l];
        const float* wl = W_fc + l * Hh;
        #pragma unroll 16
        for (int k = 0; k < Hh; ++k)
            acc += reinterpret_cast<const float*>(&s->hx[k >> 1][r])[k & 1] * wl[k];
        out[(row0 + r) * Ll + l] = acc;
    }
}

// ---------------- host launch ----------------
extern "C" void kernel_launch(void* const* d_in, const int* in_sizes, int n_in,
                              void* d_out, int out_size) {
    const float* x    = (const float*)d_in[0];
    const float* W_ih = (const float*)d_in[1];
    const float* W_hh = (const float*)d_in[2];
    const float* b_ih = (const float*)d_in[3];
    const float* b_hh = (const float*)d_in[4];
    const float* W_fc = (const float*)d_in[5];
    const float* b_fc = (const float*)d_in[6];
    float* out = (float*)d_out;

    const size_t smem = sizeof(Smem);
    cudaFuncSetAttribute(lstm_kernel, cudaFuncAttributeMaxDynamicSharedMemorySize, (int)smem);
    lstm_kernel<<<Bb / ROWS, NTHREADS, smem>>>(x, W_ih, W_hh, b_ih, b_hh, W_fc, b_fc, out);
}